// round 2
// baseline (speedup 1.0000x reference)
#include <cuda_runtime.h>
#include <math.h>

// Problem constants
#define Bb    4
#define Ss    1024
#define Dd    1024
#define Hh    16
#define KHh   4
#define HDd   64
#define Ee    8
#define HIDd  2816
#define NTOK  4096          // B*S
#define MAXROWS 9216        // 8192 routed rows + per-expert pad to 128

// ---------------- scratch (static device globals; no runtime allocation) ---------
static __device__ __align__(128) float g_xn  [NTOK * Dd];
static __device__ __align__(128) float g_q   [NTOK * Hh * HDd];
static __device__ __align__(128) float g_k   [NTOK * KHh * HDd];
static __device__ __align__(128) float g_v   [NTOK * KHh * HDd];
static __device__ __align__(128) float g_at  [NTOK * Hh * HDd];
static __device__ __align__(128) float g_h   [NTOK * Dd];
static __device__ __align__(128) float g_hn  [NTOK * Dd];
static __device__ __align__(128) float g_t1  [(size_t)MAXROWS * HIDd];
static __device__ __align__(128) float g_t3  [(size_t)MAXROWS * HIDd];
static __device__ __align__(128) float g_g2  [(size_t)MAXROWS * Dd];
static __device__ int   g_counts[Ee];
static __device__ int   g_poff  [Ee];
static __device__ int   g_pcount[Ee];
static __device__ int   g_cursor[Ee];
static __device__ int   g_perm  [MAXROWS];
static __device__ int   g_topi  [NTOK * 2];
static __device__ int   g_slot  [NTOK * 2];
static __device__ float g_tw    [NTOK * 2];

// ---------------- helpers ----------------
static __device__ __forceinline__ float warp_sum(float v) {
#pragma unroll
    for (int o = 16; o; o >>= 1) v += __shfl_xor_sync(0xffffffffu, v, o);
    return v;
}
static __device__ __forceinline__ float warp_max(float v) {
#pragma unroll
    for (int o = 16; o; o >>= 1) v = fmaxf(v, __shfl_xor_sync(0xffffffffu, v, o));
    return v;
}

// ---------------- rmsnorm: one block per row, 256 threads x float4 --------------
__global__ void rmsnorm_kernel(const float* __restrict__ x, const float* __restrict__ w,
                               float* __restrict__ o) {
    int row = blockIdx.x;
    const float* xr = x + (size_t)row * Dd;
    float4 v = *(const float4*)(xr + threadIdx.x * 4);
    float ss = v.x * v.x + v.y * v.y + v.z * v.z + v.w * v.w;
    ss = warp_sum(ss);
    __shared__ float sm[8];
    int wid = threadIdx.x >> 5, lane = threadIdx.x & 31;
    if (lane == 0) sm[wid] = ss;
    __syncthreads();
    float tot = 0.f;
#pragma unroll
    for (int i = 0; i < 8; i++) tot += sm[i];
    float inv = rsqrtf(tot * (1.0f / Dd) + 1e-5f);
    float4 wv = *(const float4*)(w + threadIdx.x * 4);
    float4 ov;
    ov.x = v.x * inv * wv.x; ov.y = v.y * inv * wv.y;
    ov.z = v.z * inv * wv.z; ov.w = v.w * inv * wv.w;
    *(float4*)(o + (size_t)row * Dd + threadIdx.x * 4) = ov;
}

// ---------------- SGEMM: C[M,N] = A[M,K] @ B[K,N] (+ R), 128x128x8, 8x8 micro ----
__global__ __launch_bounds__(256) void sgemm_kernel(
    const float* __restrict__ A, const float* __restrict__ Bm,
    const float* __restrict__ R, float* __restrict__ C,
    int M, int N, int K) {
    __shared__ float As[8][128];
    __shared__ float Bs[8][128];
    int tid = threadIdx.x;
    int tx = tid & 15, ty = tid >> 4;
    int ra = tid >> 1;           // 0..127 A row in tile
    int ca = (tid & 1) << 2;     // 0 or 4
    int rb = tid >> 5;           // 0..7
    int cb = (tid & 31) << 2;    // 0..124
    const float* Ap = A + (size_t)(blockIdx.y * 128 + ra) * K + ca;
    const float* Bp = Bm + (size_t)rb * N + (size_t)blockIdx.x * 128 + cb;

    float acc[8][8];
#pragma unroll
    for (int i = 0; i < 8; i++)
#pragma unroll
        for (int j = 0; j < 8; j++) acc[i][j] = 0.f;

    float4 av = *(const float4*)Ap;
    float4 bv = *(const float4*)Bp;
    for (int k0 = 0; k0 < K; k0 += 8) {
        As[ca + 0][ra] = av.x; As[ca + 1][ra] = av.y;
        As[ca + 2][ra] = av.z; As[ca + 3][ra] = av.w;
        *(float4*)&Bs[rb][cb] = bv;
        __syncthreads();
        if (k0 + 8 < K) {
            av = *(const float4*)(Ap + k0 + 8);
            bv = *(const float4*)(Bp + (size_t)(k0 + 8) * N);
        }
#pragma unroll
        for (int kk = 0; kk < 8; kk++) {
            float a[8], b[8];
            *(float4*)(a)     = *(const float4*)&As[kk][ty * 8];
            *(float4*)(a + 4) = *(const float4*)&As[kk][ty * 8 + 4];
            *(float4*)(b)     = *(const float4*)&Bs[kk][tx * 8];
            *(float4*)(b + 4) = *(const float4*)&Bs[kk][tx * 8 + 4];
#pragma unroll
            for (int i = 0; i < 8; i++)
#pragma unroll
                for (int j = 0; j < 8; j++) acc[i][j] += a[i] * b[j];
        }
        __syncthreads();
    }
#pragma unroll
    for (int i = 0; i < 8; i++) {
        size_t row = (size_t)blockIdx.y * 128 + ty * 8 + i;
        float* Cp = C + row * N + (size_t)blockIdx.x * 128 + tx * 8;
#pragma unroll
        for (int j = 0; j < 8; j += 4) {
            float4 ov;
            ov.x = acc[i][j]; ov.y = acc[i][j + 1];
            ov.z = acc[i][j + 2]; ov.w = acc[i][j + 3];
            if (R) {
                float4 rv = *(const float4*)(R + row * N + (size_t)blockIdx.x * 128 + tx * 8 + j);
                ov.x += rv.x; ov.y += rv.y; ov.z += rv.z; ov.w += rv.w;
            }
            *(float4*)(Cp + j) = ov;
        }
    }
}

// ---------------- MoE SGEMM: per-expert segments, optional row gather via perm ---
__global__ __launch_bounds__(256) void moe_sgemm_kernel(
    const float* __restrict__ A, const float* __restrict__ Ball,
    float* __restrict__ C, int K, int N, int usePerm) {
    int e = blockIdx.z;
    int pc = g_pcount[e];
    if ((int)(blockIdx.y * 128) >= pc) return;
    int rbase = g_poff[e] + blockIdx.y * 128;
    const float* Bm = Ball + (size_t)e * K * N;

    __shared__ float As[8][128];
    __shared__ float Bs[8][128];
    int tid = threadIdx.x;
    int tx = tid & 15, ty = tid >> 4;
    int ra = tid >> 1;
    int ca = (tid & 1) << 2;
    int rb = tid >> 5;
    int cb = (tid & 31) << 2;

    int rglob = rbase + ra;
    int arow = usePerm ? g_perm[rglob] : rglob;
    const float* Ap = (arow >= 0) ? (A + (size_t)arow * K + ca) : nullptr;
    const float* Bp = Bm + (size_t)rb * N + (size_t)blockIdx.x * 128 + cb;

    float acc[8][8];
#pragma unroll
    for (int i = 0; i < 8; i++)
#pragma unroll
        for (int j = 0; j < 8; j++) acc[i][j] = 0.f;

    float4 av = make_float4(0.f, 0.f, 0.f, 0.f);
    if (Ap) av = *(const float4*)Ap;
    float4 bv = *(const float4*)Bp;
    for (int k0 = 0; k0 < K; k0 += 8) {
        As[ca + 0][ra] = av.x; As[ca + 1][ra] = av.y;
        As[ca + 2][ra] = av.z; As[ca + 3][ra] = av.w;
        *(float4*)&Bs[rb][cb] = bv;
        __syncthreads();
        if (k0 + 8 < K) {
            if (Ap) av = *(const float4*)(Ap + k0 + 8);
            bv = *(const float4*)(Bp + (size_t)(k0 + 8) * N);
        }
#pragma unroll
        for (int kk = 0; kk < 8; kk++) {
            float a[8], b[8];
            *(float4*)(a)     = *(const float4*)&As[kk][ty * 8];
            *(float4*)(a + 4) = *(const float4*)&As[kk][ty * 8 + 4];
            *(float4*)(b)     = *(const float4*)&Bs[kk][tx * 8];
            *(float4*)(b + 4) = *(const float4*)&Bs[kk][tx * 8 + 4];
#pragma unroll
            for (int i = 0; i < 8; i++)
#pragma unroll
                for (int j = 0; j < 8; j++) acc[i][j] += a[i] * b[j];
        }
        __syncthreads();
    }
#pragma unroll
    for (int i = 0; i < 8; i++) {
        size_t row = (size_t)rbase + ty * 8 + i;
        float* Cp = C + row * N + (size_t)blockIdx.x * 128 + tx * 8;
#pragma unroll
        for (int j = 0; j < 8; j += 4) {
            float4 ov;
            ov.x = acc[i][j]; ov.y = acc[i][j + 1];
            ov.z = acc[i][j + 2]; ov.w = acc[i][j + 3];
            *(float4*)(Cp + j) = ov;
        }
    }
}

// ---------------- RoPE (in place) ----------------
__global__ void rope_kernel(float* __restrict__ t, const float* __restrict__ cosb,
                            const float* __restrict__ sinb, int nheads) {
    int row = blockIdx.x;
    int s = row & (Ss - 1);
    int h = threadIdx.x >> 5;
    int i = threadIdx.x & 31;
    float c = cosb[s * 32 + i];
    float sn = sinb[s * 32 + i];
    float* p = t + (size_t)row * nheads * HDd + h * HDd + 2 * i;
    float a = p[0], b = p[1];
    p[0] = a * c - b * sn;
    p[1] = a * sn + b * c;
}

// ---------------- flash attention: warp per q-row, 64-key smem tiles ------------
__global__ __launch_bounds__(256) void attn_kernel(
    const float* __restrict__ q, const float* __restrict__ k,
    const float* __restrict__ v, float* __restrict__ o) {
    __shared__ float Ks[64][68];
    __shared__ float Vs[64][68];
    __shared__ float Ps[8][64];
    int b = blockIdx.z, h = blockIdx.y;
    int w = threadIdx.x >> 5, lane = threadIdx.x & 31;
    int qrow = blockIdx.x * 8 + w;
    int kvh = h >> 2;   // N_REP = 4

    const float* qp = q + (size_t)(b * Ss + qrow) * (Hh * HDd) + h * HDd;
    float qr[64];
#pragma unroll
    for (int d = 0; d < 64; d += 4) {
        float4 t4 = *(const float4*)(qp + d);
        qr[d] = t4.x * 0.125f; qr[d + 1] = t4.y * 0.125f;
        qr[d + 2] = t4.z * 0.125f; qr[d + 3] = t4.w * 0.125f;
    }
    float m = -1e30f, l = 0.f, acc0 = 0.f, acc1 = 0.f;
    int dd = lane * 2;
    int ntiles = (blockIdx.x >> 3) + 1;
    int tid = threadIdx.x;
    int lkey = tid >> 2;
    int lcol = (tid & 3) * 16;

    for (int t = 0; t < ntiles; t++) {
        int kb = t * 64;
        const float* kp = k + (size_t)(b * Ss + kb + lkey) * (KHh * HDd) + kvh * HDd + lcol;
        const float* vp = v + (size_t)(b * Ss + kb + lkey) * (KHh * HDd) + kvh * HDd + lcol;
#pragma unroll
        for (int i = 0; i < 16; i += 4) {
            *(float4*)&Ks[lkey][lcol + i] = *(const float4*)(kp + i);
            *(float4*)&Vs[lkey][lcol + i] = *(const float4*)(vp + i);
        }
        __syncthreads();

        float s0 = 0.f, s1 = 0.f;
#pragma unroll
        for (int d = 0; d < 64; d += 4) {
            float4 k0v = *(const float4*)&Ks[lane][d];
            float4 k1v = *(const float4*)&Ks[lane + 32][d];
            s0 += qr[d] * k0v.x + qr[d + 1] * k0v.y + qr[d + 2] * k0v.z + qr[d + 3] * k0v.w;
            s1 += qr[d] * k1v.x + qr[d + 1] * k1v.y + qr[d + 2] * k1v.z + qr[d + 3] * k1v.w;
        }
        int kg = kb + lane;
        if (kg > qrow)      s0 = -1e30f;
        if (kg + 32 > qrow) s1 = -1e30f;

        float mt = warp_max(fmaxf(s0, s1));
        float mnew = fmaxf(m, mt);
        float corr = __expf(m - mnew);
        float p0 = __expf(s0 - mnew);
        float p1 = __expf(s1 - mnew);
        float ps = warp_sum(p0 + p1);
        l = l * corr + ps;
        m = mnew;
        Ps[w][lane] = p0; Ps[w][lane + 32] = p1;
        __syncwarp();
        acc0 *= corr; acc1 *= corr;
#pragma unroll
        for (int kk = 0; kk < 64; kk += 4) {
            float4 pv = *(const float4*)&Ps[w][kk];
            float2 v0 = *(const float2*)&Vs[kk + 0][dd];
            float2 v1 = *(const float2*)&Vs[kk + 1][dd];
            float2 v2 = *(const float2*)&Vs[kk + 2][dd];
            float2 v3 = *(const float2*)&Vs[kk + 3][dd];
            acc0 += pv.x * v0.x + pv.y * v1.x + pv.z * v2.x + pv.w * v3.x;
            acc1 += pv.x * v0.y + pv.y * v1.y + pv.z * v2.y + pv.w * v3.y;
        }
        __syncthreads();
    }
    float inv = 1.f / l;
    float* op = o + (size_t)(b * Ss + qrow) * (Hh * HDd) + h * HDd + dd;
    op[0] = acc0 * inv;
    op[1] = acc1 * inv;
}

// ---------------- gating: warp per token ----------------
__global__ void gate_kernel(const float* __restrict__ hn, const float* __restrict__ gw) {
    int warp = threadIdx.x >> 5, lane = threadIdx.x & 31;
    int t = blockIdx.x * 4 + warp;
    const float* xr = hn + (size_t)t * Dd;
    float xv[32];
#pragma unroll
    for (int i = 0; i < 32; i++) xv[i] = xr[lane + 32 * i];
    float lg[Ee];
#pragma unroll
    for (int e = 0; e < Ee; e++) {
        float p = 0.f;
#pragma unroll
        for (int i = 0; i < 32; i++) p += xv[i] * gw[(lane + 32 * i) * Ee + e];
        lg[e] = warp_sum(p);
    }
    if (lane == 0) {
        float mx = lg[0];
#pragma unroll
        for (int e = 1; e < Ee; e++) mx = fmaxf(mx, lg[e]);
        float pr[Ee];
#pragma unroll
        for (int e = 0; e < Ee; e++) pr[e] = __expf(lg[e] - mx);
        int i1 = 0;
#pragma unroll
        for (int e = 1; e < Ee; e++) if (pr[e] > pr[i1]) i1 = e;
        int i2 = -1;
#pragma unroll
        for (int e = 0; e < Ee; e++)
            if (e != i1 && (i2 < 0 || pr[e] > pr[i2])) i2 = e;
        float wsum = pr[i1] + pr[i2];
        g_topi[2 * t] = i1; g_topi[2 * t + 1] = i2;
        g_tw[2 * t] = pr[i1] / wsum; g_tw[2 * t + 1] = pr[i2] / wsum;
        atomicAdd(&g_counts[i1], 1);
        atomicAdd(&g_counts[i2], 1);
    }
}

// ---------------- routing bookkeeping ----------------
__global__ void setup_kernel() {
    if (threadIdx.x < Ee) g_counts[threadIdx.x] = 0;
}
__global__ void scan_kernel() {
    if (threadIdx.x == 0) {
        int off = 0;
        for (int e = 0; e < Ee; e++) {
            g_poff[e] = off;
            int pcv = ((g_counts[e] + 127) >> 7) << 7;
            g_pcount[e] = pcv;
            off += pcv;
            g_cursor[e] = 0;
        }
    }
}
__global__ void initperm_kernel() {
    int i = blockIdx.x * 256 + threadIdx.x;
    if (i < MAXROWS) g_perm[i] = -1;
}
__global__ void scatter_kernel() {
    int t = blockIdx.x * 256 + threadIdx.x;
    if (t < NTOK) {
#pragma unroll
        for (int j = 0; j < 2; j++) {
            int e = g_topi[2 * t + j];
            int pos = g_poff[e] + atomicAdd(&g_cursor[e], 1);
            g_perm[pos] = t;
            g_slot[2 * t + j] = pos;
        }
    }
}

// ---------------- silu(t1) * t3 -> t1 ----------------
__global__ void silu_mul_kernel() {
    size_t i = ((size_t)blockIdx.x * 256 + threadIdx.x) * 4;
    float4 a = *(float4*)&g_t1[i];
    float4 c = *(float4*)&g_t3[i];
    a.x = a.x / (1.f + __expf(-a.x)) * c.x;
    a.y = a.y / (1.f + __expf(-a.y)) * c.y;
    a.z = a.z / (1.f + __expf(-a.z)) * c.z;
    a.w = a.w / (1.f + __expf(-a.w)) * c.w;
    *(float4*)&g_t1[i] = a;
}

// ---------------- final combine: out = h + w0*g2[slot0] + w1*g2[slot1] ----------
__global__ void combine_kernel(float* __restrict__ out) {
    int t = blockIdx.x;
    int d = threadIdx.x * 4;
    float w0 = g_tw[2 * t], w1 = g_tw[2 * t + 1];
    int s0 = g_slot[2 * t], s1 = g_slot[2 * t + 1];
    float4 hv = *(float4*)&g_h[(size_t)t * Dd + d];
    float4 a  = *(float4*)&g_g2[(size_t)s0 * Dd + d];
    float4 b  = *(float4*)&g_g2[(size_t)s1 * Dd + d];
    float4 ov;
    ov.x = hv.x + w0 * a.x + w1 * b.x;
    ov.y = hv.y + w0 * a.y + w1 * b.y;
    ov.z = hv.z + w0 * a.z + w1 * b.z;
    ov.w = hv.w + w0 * a.w + w1 * b.w;
    *(float4*)(out + (size_t)t * Dd + d) = ov;
}

// ---------------- launch ----------------
extern "C" void kernel_launch(void* const* d_in, const int* in_sizes, int n_in,
                              void* d_out, int out_size) {
    const float* x    = (const float*)d_in[0];
    // d_in[1] = start_pos (0), d_in[2] = mask (causal, reconstructed) — unused
    const float* fcos = (const float*)d_in[3];
    const float* fsin = (const float*)d_in[4];
    const float* anw  = (const float*)d_in[5];
    const float* fnw  = (const float*)d_in[6];
    const float* wq   = (const float*)d_in[7];
    const float* wk   = (const float*)d_in[8];
    const float* wv   = (const float*)d_in[9];
    const float* wo   = (const float*)d_in[10];
    const float* gw   = (const float*)d_in[11];
    const float* w1e  = (const float*)d_in[12];
    const float* w2e  = (const float*)d_in[13];
    const float* w3e  = (const float*)d_in[14];
    float* out = (float*)d_out;

    void* p;
    float *xn, *qb, *kb, *vb, *ab, *hb, *hnb, *t1, *t3, *g2;
    cudaGetSymbolAddress(&p, g_xn); xn  = (float*)p;
    cudaGetSymbolAddress(&p, g_q);  qb  = (float*)p;
    cudaGetSymbolAddress(&p, g_k);  kb  = (float*)p;
    cudaGetSymbolAddress(&p, g_v);  vb  = (float*)p;
    cudaGetSymbolAddress(&p, g_at); ab  = (float*)p;
    cudaGetSymbolAddress(&p, g_h);  hb  = (float*)p;
    cudaGetSymbolAddress(&p, g_hn); hnb = (float*)p;
    cudaGetSymbolAddress(&p, g_t1); t1  = (float*)p;
    cudaGetSymbolAddress(&p, g_t3); t3  = (float*)p;
    cudaGetSymbolAddress(&p, g_g2); g2  = (float*)p;

    setup_kernel<<<1, 32>>>();

    rmsnorm_kernel<<<NTOK, 256>>>(x, anw, xn);

    dim3 gq(1024 / 128, NTOK / 128);
    sgemm_kernel<<<gq, 256>>>(xn, wq, nullptr, qb, NTOK, 1024, 1024);
    dim3 gk(256 / 128, NTOK / 128);
    sgemm_kernel<<<gk, 256>>>(xn, wk, nullptr, kb, NTOK, 256, 1024);
    sgemm_kernel<<<gk, 256>>>(xn, wv, nullptr, vb, NTOK, 256, 1024);

    rope_kernel<<<NTOK, Hh * 32>>>(qb, fcos, fsin, Hh);
    rope_kernel<<<NTOK, KHh * 32>>>(kb, fcos, fsin, KHh);

    dim3 ga(Ss / 8, Hh, Bb);
    attn_kernel<<<ga, 256>>>(qb, kb, vb, ab);

    sgemm_kernel<<<gq, 256>>>(ab, wo, x, hb, NTOK, 1024, 1024);

    rmsnorm_kernel<<<NTOK, 256>>>(hb, fnw, hnb);

    gate_kernel<<<NTOK / 4, 128>>>(hnb, gw);
    scan_kernel<<<1, 32>>>();
    initperm_kernel<<<(MAXROWS + 255) / 256, 256>>>();
    scatter_kernel<<<NTOK / 256, 256>>>();

    dim3 gm1(HIDd / 128, 32, Ee);
    moe_sgemm_kernel<<<gm1, 256>>>(hnb, w1e, t1, Dd, HIDd, 1);
    moe_sgemm_kernel<<<gm1, 256>>>(hnb, w3e, t3, Dd, HIDd, 1);

    silu_mul_kernel<<<(MAXROWS / 4) * (HIDd / 256), 256>>>();

    dim3 gm2(Dd / 128, 32, Ee);
    moe_sgemm_kernel<<<gm2, 256>>>(t1, w2e, g2, HIDd, Dd, 0);

    combine_kernel<<<NTOK, 256>>>(out);
}

// round 3
// speedup vs baseline: 2.1307x; 2.1307x over previous
#include <cuda_runtime.h>
#include <math.h>
#include <stdint.h>

// Problem constants
#define Bb    4
#define Ss    1024
#define Dd    1024
#define Hh    16
#define KHh   4
#define HDd   64
#define Ee    8
#define HIDd  2816
#define NTOK  4096
#define MAXROWS 9216

// ---------------- scratch ----------------
static __device__ __align__(128) float g_xn  [NTOK * Dd];
static __device__ __align__(128) float g_q   [NTOK * Hh * HDd];
static __device__ __align__(128) float g_k   [NTOK * KHh * HDd];
static __device__ __align__(128) float g_v   [NTOK * KHh * HDd];
static __device__ __align__(128) float g_at  [NTOK * Hh * HDd];
static __device__ __align__(128) float g_h   [NTOK * Dd];
static __device__ __align__(128) float g_hn  [NTOK * Dd];
static __device__ __align__(128) float g_t1  [(size_t)MAXROWS * HIDd];
static __device__ __align__(128) float g_t3  [(size_t)MAXROWS * HIDd];
static __device__ __align__(128) float g_g2  [(size_t)MAXROWS * Dd];
static __device__ int   g_counts[Ee];
static __device__ int   g_poff  [Ee];
static __device__ int   g_pcount[Ee];
static __device__ int   g_cursor[Ee];
static __device__ int   g_perm  [MAXROWS];
static __device__ int   g_topi  [NTOK * 2];
static __device__ int   g_slot  [NTOK * 2];
static __device__ float g_tw    [NTOK * 2];

// ---------------- helpers ----------------
static __device__ __forceinline__ float warp_sum(float v) {
#pragma unroll
    for (int o = 16; o; o >>= 1) v += __shfl_xor_sync(0xffffffffu, v, o);
    return v;
}
static __device__ __forceinline__ float warp_max(float v) {
#pragma unroll
    for (int o = 16; o; o >>= 1) v = fmaxf(v, __shfl_xor_sync(0xffffffffu, v, o));
    return v;
}
static __device__ __forceinline__ uint32_t f2tf(float f) {
    uint32_t u;
    asm("cvt.rna.tf32.f32 %0, %1;" : "=r"(u) : "f"(f));
    return u;
}
static __device__ __forceinline__ void mma8(float* c, const uint32_t* a, const uint32_t* b) {
    asm volatile(
        "mma.sync.aligned.m16n8k8.row.col.f32.tf32.tf32.f32 "
        "{%0,%1,%2,%3}, {%4,%5,%6,%7}, {%8,%9}, {%0,%1,%2,%3};"
        : "+f"(c[0]), "+f"(c[1]), "+f"(c[2]), "+f"(c[3])
        : "r"(a[0]), "r"(a[1]), "r"(a[2]), "r"(a[3]), "r"(b[0]), "r"(b[1]));
}

// ---------------- rmsnorm ----------------
__global__ void rmsnorm_kernel(const float* __restrict__ x, const float* __restrict__ w,
                               float* __restrict__ o) {
    int row = blockIdx.x;
    const float* xr = x + (size_t)row * Dd;
    float4 v = *(const float4*)(xr + threadIdx.x * 4);
    float ss = v.x * v.x + v.y * v.y + v.z * v.z + v.w * v.w;
    ss = warp_sum(ss);
    __shared__ float sm[8];
    int wid = threadIdx.x >> 5, lane = threadIdx.x & 31;
    if (lane == 0) sm[wid] = ss;
    __syncthreads();
    float tot = 0.f;
#pragma unroll
    for (int i = 0; i < 8; i++) tot += sm[i];
    float inv = rsqrtf(tot * (1.0f / Dd) + 1e-5f);
    float4 wv = *(const float4*)(w + threadIdx.x * 4);
    float4 ov;
    ov.x = v.x * inv * wv.x; ov.y = v.y * inv * wv.y;
    ov.z = v.z * inv * wv.z; ov.w = v.w * inv * wv.w;
    *(float4*)(o + (size_t)row * Dd + threadIdx.x * 4) = ov;
}

// ---------------- tf32 tensor-core GEMM: C[M,N] = A @ B (+R), 128x128x32 -------
__global__ __launch_bounds__(256, 1) void tf32_gemm_kernel(
    const float* __restrict__ A, const float* __restrict__ Bm,
    const float* __restrict__ R, float* __restrict__ C, int N, int K) {
    __shared__ uint32_t As[128][36];
    __shared__ uint32_t Bs[32][136];
    int tid = threadIdx.x;
    int wid = tid >> 5, lane = tid & 31;
    int wm = (wid >> 2) << 6;        // 0 / 64
    int wn = (wid & 3) << 5;         // 0..96
    int g = lane >> 2, tg = lane & 3;
    int ar = tid >> 1, ak = (tid & 1) << 4;
    int bk = tid >> 3, bn = (tid & 7) << 4;
    const float* Ap = A + (size_t)(blockIdx.y * 128 + ar) * K + ak;
    const float* Bp = Bm + (size_t)bk * N + blockIdx.x * 128 + bn;

    float acc[4][4][4];
#pragma unroll
    for (int i = 0; i < 4; i++)
#pragma unroll
        for (int j = 0; j < 4; j++)
#pragma unroll
            for (int q = 0; q < 4; q++) acc[i][j][q] = 0.f;

    float4 avs[4], bvs[4];
#pragma unroll
    for (int i = 0; i < 4; i++) {
        avs[i] = *(const float4*)(Ap + i * 4);
        bvs[i] = *(const float4*)(Bp + i * 4);
    }
    for (int k0 = 0; k0 < K; k0 += 32) {
#pragma unroll
        for (int i = 0; i < 4; i++) {
            uint4 ua; ua.x = f2tf(avs[i].x); ua.y = f2tf(avs[i].y);
            ua.z = f2tf(avs[i].z); ua.w = f2tf(avs[i].w);
            *(uint4*)&As[ar][ak + i * 4] = ua;
            uint4 ub; ub.x = f2tf(bvs[i].x); ub.y = f2tf(bvs[i].y);
            ub.z = f2tf(bvs[i].z); ub.w = f2tf(bvs[i].w);
            *(uint4*)&Bs[bk][bn + i * 4] = ub;
        }
        __syncthreads();
        if (k0 + 32 < K) {
#pragma unroll
            for (int i = 0; i < 4; i++) {
                avs[i] = *(const float4*)(Ap + k0 + 32 + i * 4);
                bvs[i] = *(const float4*)(Bp + (size_t)(k0 + 32) * N + i * 4);
            }
        }
#pragma unroll
        for (int ks = 0; ks < 4; ks++) {
            int k8 = ks * 8;
            uint32_t a[4][4], bf[4][2];
#pragma unroll
            for (int mf = 0; mf < 4; mf++) {
                int mr = wm + mf * 16 + g;
                a[mf][0] = As[mr][k8 + tg];
                a[mf][1] = As[mr + 8][k8 + tg];
                a[mf][2] = As[mr][k8 + tg + 4];
                a[mf][3] = As[mr + 8][k8 + tg + 4];
            }
#pragma unroll
            for (int nf = 0; nf < 4; nf++) {
                int nc = wn + nf * 8 + g;
                bf[nf][0] = Bs[k8 + tg][nc];
                bf[nf][1] = Bs[k8 + tg + 4][nc];
            }
#pragma unroll
            for (int mf = 0; mf < 4; mf++)
#pragma unroll
                for (int nf = 0; nf < 4; nf++) mma8(acc[mf][nf], a[mf], bf[nf]);
        }
        __syncthreads();
    }
#pragma unroll
    for (int mf = 0; mf < 4; mf++)
#pragma unroll
        for (int nf = 0; nf < 4; nf++) {
            size_t row = (size_t)blockIdx.y * 128 + wm + mf * 16 + g;
            int col = blockIdx.x * 128 + wn + nf * 8 + 2 * tg;
            float2 v01 = make_float2(acc[mf][nf][0], acc[mf][nf][1]);
            float2 v23 = make_float2(acc[mf][nf][2], acc[mf][nf][3]);
            if (R) {
                float2 r0 = *(const float2*)(R + row * N + col);
                float2 r1 = *(const float2*)(R + (row + 8) * N + col);
                v01.x += r0.x; v01.y += r0.y; v23.x += r1.x; v23.y += r1.y;
            }
            *(float2*)(C + row * N + col) = v01;
            *(float2*)(C + (row + 8) * N + col) = v23;
        }
}

// ---------------- tf32 MoE GEMM: per-expert segments, optional perm gather ------
__global__ __launch_bounds__(256, 1) void tf32_moe_gemm_kernel(
    const float* __restrict__ A, const float* __restrict__ Ball,
    float* __restrict__ C, int N, int K, int usePerm) {
    int e = blockIdx.z;
    int pc = g_pcount[e];
    if ((int)(blockIdx.y * 128) >= pc) return;
    int rbase = g_poff[e] + blockIdx.y * 128;
    const float* Bm = Ball + (size_t)e * K * N;

    __shared__ uint32_t As[128][36];
    __shared__ uint32_t Bs[32][136];
    int tid = threadIdx.x;
    int wid = tid >> 5, lane = tid & 31;
    int wm = (wid >> 2) << 6;
    int wn = (wid & 3) << 5;
    int g = lane >> 2, tg = lane & 3;
    int ar = tid >> 1, ak = (tid & 1) << 4;
    int bk = tid >> 3, bn = (tid & 7) << 4;

    int arow = usePerm ? g_perm[rbase + ar] : (rbase + ar);
    const float* Ap = (arow >= 0) ? (A + (size_t)arow * K + ak) : nullptr;
    const float* Bp = Bm + (size_t)bk * N + blockIdx.x * 128 + bn;

    float acc[4][4][4];
#pragma unroll
    for (int i = 0; i < 4; i++)
#pragma unroll
        for (int j = 0; j < 4; j++)
#pragma unroll
            for (int q = 0; q < 4; q++) acc[i][j][q] = 0.f;

    float4 avs[4], bvs[4];
#pragma unroll
    for (int i = 0; i < 4; i++) {
        avs[i] = Ap ? *(const float4*)(Ap + i * 4) : make_float4(0.f, 0.f, 0.f, 0.f);
        bvs[i] = *(const float4*)(Bp + i * 4);
    }
    for (int k0 = 0; k0 < K; k0 += 32) {
#pragma unroll
        for (int i = 0; i < 4; i++) {
            uint4 ua; ua.x = f2tf(avs[i].x); ua.y = f2tf(avs[i].y);
            ua.z = f2tf(avs[i].z); ua.w = f2tf(avs[i].w);
            *(uint4*)&As[ar][ak + i * 4] = ua;
            uint4 ub; ub.x = f2tf(bvs[i].x); ub.y = f2tf(bvs[i].y);
            ub.z = f2tf(bvs[i].z); ub.w = f2tf(bvs[i].w);
            *(uint4*)&Bs[bk][bn + i * 4] = ub;
        }
        __syncthreads();
        if (k0 + 32 < K) {
#pragma unroll
            for (int i = 0; i < 4; i++) {
                if (Ap) avs[i] = *(const float4*)(Ap + k0 + 32 + i * 4);
                bvs[i] = *(const float4*)(Bp + (size_t)(k0 + 32) * N + i * 4);
            }
        }
#pragma unroll
        for (int ks = 0; ks < 4; ks++) {
            int k8 = ks * 8;
            uint32_t a[4][4], bf[4][2];
#pragma unroll
            for (int mf = 0; mf < 4; mf++) {
                int mr = wm + mf * 16 + g;
                a[mf][0] = As[mr][k8 + tg];
                a[mf][1] = As[mr + 8][k8 + tg];
                a[mf][2] = As[mr][k8 + tg + 4];
                a[mf][3] = As[mr + 8][k8 + tg + 4];
            }
#pragma unroll
            for (int nf = 0; nf < 4; nf++) {
                int nc = wn + nf * 8 + g;
                bf[nf][0] = Bs[k8 + tg][nc];
                bf[nf][1] = Bs[k8 + tg + 4][nc];
            }
#pragma unroll
            for (int mf = 0; mf < 4; mf++)
#pragma unroll
                for (int nf = 0; nf < 4; nf++) mma8(acc[mf][nf], a[mf], bf[nf]);
        }
        __syncthreads();
    }
#pragma unroll
    for (int mf = 0; mf < 4; mf++)
#pragma unroll
        for (int nf = 0; nf < 4; nf++) {
            size_t row = (size_t)rbase + wm + mf * 16 + g;
            int col = blockIdx.x * 128 + wn + nf * 8 + 2 * tg;
            *(float2*)(C + row * N + col) =
                make_float2(acc[mf][nf][0], acc[mf][nf][1]);
            *(float2*)(C + (row + 8) * N + col) =
                make_float2(acc[mf][nf][2], acc[mf][nf][3]);
        }
}

// ---------------- RoPE ----------------
__global__ void rope_kernel(float* __restrict__ t, const float* __restrict__ cosb,
                            const float* __restrict__ sinb, int nheads) {
    int row = blockIdx.x;
    int s = row & (Ss - 1);
    int h = threadIdx.x >> 5;
    int i = threadIdx.x & 31;
    float c = cosb[s * 32 + i];
    float sn = sinb[s * 32 + i];
    float* p = t + (size_t)row * nheads * HDd + h * HDd + 2 * i;
    float a = p[0], b = p[1];
    p[0] = a * c - b * sn;
    p[1] = a * sn + b * c;
}

// ---------------- flash attention: 32 q-rows/block, K/V time-share smem ---------
__global__ __launch_bounds__(256) void attn_kernel(
    const float* __restrict__ q, const float* __restrict__ k,
    const float* __restrict__ v, float* __restrict__ o) {
    __shared__ float Qs[32][64];
    __shared__ float KV[64][68];
    __shared__ float Ps[8][4][64];
    int b = blockIdx.z, h = blockIdx.y;
    int tid = threadIdx.x, w = tid >> 5, lane = tid & 31;
    int qbase = blockIdx.x * 32;
    int kvh = h >> 2;

    {   // load scaled Q tile
        int r = tid >> 3;
        int c = (tid & 7) * 8;
        const float* qp = q + (size_t)(b * Ss + qbase + r) * (Hh * HDd) + h * HDd + c;
        float4 t0 = *(const float4*)qp;
        float4 t1 = *(const float4*)(qp + 4);
        Qs[r][c + 0] = t0.x * 0.125f; Qs[r][c + 1] = t0.y * 0.125f;
        Qs[r][c + 2] = t0.z * 0.125f; Qs[r][c + 3] = t0.w * 0.125f;
        Qs[r][c + 4] = t1.x * 0.125f; Qs[r][c + 5] = t1.y * 0.125f;
        Qs[r][c + 6] = t1.z * 0.125f; Qs[r][c + 7] = t1.w * 0.125f;
    }
    float m[4], l[4], a0[4], a1[4];
#pragma unroll
    for (int r = 0; r < 4; r++) { m[r] = -1e30f; l[r] = 0.f; a0[r] = 0.f; a1[r] = 0.f; }
    int dd = lane * 2;
    int ntiles = qbase / 64 + 1;
    int lkey = tid >> 2, lcol = (tid & 3) * 16;
    __syncthreads();

    for (int t = 0; t < ntiles; t++) {
        int kb = t * 64;
        const float* kp = k + (size_t)(b * Ss + kb + lkey) * (KHh * HDd) + kvh * HDd + lcol;
#pragma unroll
        for (int i = 0; i < 16; i += 4)
            *(float4*)&KV[lkey][lcol + i] = *(const float4*)(kp + i);
        __syncthreads();

        float corr[4];
#pragma unroll
        for (int r = 0; r < 4; r++) {
            float s0 = 0.f, s1 = 0.f;
            const float* qrow = &Qs[w * 4 + r][0];
#pragma unroll
            for (int d = 0; d < 64; d += 4) {
                float4 q4 = *(const float4*)(qrow + d);
                float4 k0v = *(const float4*)&KV[lane][d];
                float4 k1v = *(const float4*)&KV[lane + 32][d];
                s0 += q4.x * k0v.x + q4.y * k0v.y + q4.z * k0v.z + q4.w * k0v.w;
                s1 += q4.x * k1v.x + q4.y * k1v.y + q4.z * k1v.z + q4.w * k1v.w;
            }
            int row = qbase + w * 4 + r;
            if (kb + lane > row)      s0 = -1e30f;
            if (kb + lane + 32 > row) s1 = -1e30f;
            float mt = warp_max(fmaxf(s0, s1));
            float mnew = fmaxf(m[r], mt);
            corr[r] = __expf(m[r] - mnew);
            float p0 = __expf(s0 - mnew);
            float p1 = __expf(s1 - mnew);
            l[r] = l[r] * corr[r] + warp_sum(p0 + p1);
            m[r] = mnew;
            Ps[w][r][lane] = p0;
            Ps[w][r][lane + 32] = p1;
        }
        __syncthreads();

        const float* vp = v + (size_t)(b * Ss + kb + lkey) * (KHh * HDd) + kvh * HDd + lcol;
#pragma unroll
        for (int i = 0; i < 16; i += 4)
            *(float4*)&KV[lkey][lcol + i] = *(const float4*)(vp + i);
        __syncthreads();

#pragma unroll
        for (int r = 0; r < 4; r++) { a0[r] *= corr[r]; a1[r] *= corr[r]; }
#pragma unroll
        for (int kk = 0; kk < 64; kk += 4) {
            float2 v0 = *(const float2*)&KV[kk + 0][dd];
            float2 v1 = *(const float2*)&KV[kk + 1][dd];
            float2 v2 = *(const float2*)&KV[kk + 2][dd];
            float2 v3 = *(const float2*)&KV[kk + 3][dd];
#pragma unroll
            for (int r = 0; r < 4; r++) {
                float4 p4 = *(const float4*)&Ps[w][r][kk];
                a0[r] += p4.x * v0.x + p4.y * v1.x + p4.z * v2.x + p4.w * v3.x;
                a1[r] += p4.x * v0.y + p4.y * v1.y + p4.z * v2.y + p4.w * v3.y;
            }
        }
        __syncthreads();
    }
#pragma unroll
    for (int r = 0; r < 4; r++) {
        float inv = 1.f / l[r];
        int row = qbase + w * 4 + r;
        float* op = o + (size_t)(b * Ss + row) * (Hh * HDd) + h * HDd + dd;
        op[0] = a0[r] * inv;
        op[1] = a1[r] * inv;
    }
}

// ---------------- gating ----------------
__global__ void gate_kernel(const float* __restrict__ hn, const float* __restrict__ gw) {
    int warp = threadIdx.x >> 5, lane = threadIdx.x & 31;
    int t = blockIdx.x * 4 + warp;
    const float* xr = hn + (size_t)t * Dd;
    float xv[32];
#pragma unroll
    for (int i = 0; i < 32; i++) xv[i] = xr[lane + 32 * i];
    float lg[Ee];
#pragma unroll
    for (int e = 0; e < Ee; e++) {
        float p = 0.f;
#pragma unroll
        for (int i = 0; i < 32; i++) p += xv[i] * gw[(lane + 32 * i) * Ee + e];
        lg[e] = warp_sum(p);
    }
    if (lane == 0) {
        float mx = lg[0];
#pragma unroll
        for (int e = 1; e < Ee; e++) mx = fmaxf(mx, lg[e]);
        float pr[Ee];
#pragma unroll
        for (int e = 0; e < Ee; e++) pr[e] = __expf(lg[e] - mx);
        int i1 = 0;
#pragma unroll
        for (int e = 1; e < Ee; e++) if (pr[e] > pr[i1]) i1 = e;
        int i2 = -1;
#pragma unroll
        for (int e = 0; e < Ee; e++)
            if (e != i1 && (i2 < 0 || pr[e] > pr[i2])) i2 = e;
        float wsum = pr[i1] + pr[i2];
        g_topi[2 * t] = i1; g_topi[2 * t + 1] = i2;
        g_tw[2 * t] = pr[i1] / wsum; g_tw[2 * t + 1] = pr[i2] / wsum;
        atomicAdd(&g_counts[i1], 1);
        atomicAdd(&g_counts[i2], 1);
    }
}

// ---------------- routing bookkeeping ----------------
__global__ void setup_kernel() {
    if (threadIdx.x < Ee) g_counts[threadIdx.x] = 0;
}
__global__ void scan_kernel() {
    if (threadIdx.x == 0) {
        int off = 0;
        for (int e = 0; e < Ee; e++) {
            g_poff[e] = off;
            int pcv = ((g_counts[e] + 127) >> 7) << 7;
            g_pcount[e] = pcv;
            off += pcv;
            g_cursor[e] = 0;
        }
    }
}
__global__ void initperm_kernel() {
    int i = blockIdx.x * 256 + threadIdx.x;
    if (i < MAXROWS) g_perm[i] = -1;
}
__global__ void scatter_kernel() {
    int t = blockIdx.x * 256 + threadIdx.x;
    if (t < NTOK) {
#pragma unroll
        for (int j = 0; j < 2; j++) {
            int e = g_topi[2 * t + j];
            int pos = g_poff[e] + atomicAdd(&g_cursor[e], 1);
            g_perm[pos] = t;
            g_slot[2 * t + j] = pos;
        }
    }
}

// ---------------- silu(t1) * t3 -> t1 ----------------
__global__ void silu_mul_kernel() {
    size_t i = ((size_t)blockIdx.x * 256 + threadIdx.x) * 4;
    float4 a = *(float4*)&g_t1[i];
    float4 c = *(float4*)&g_t3[i];
    a.x = a.x / (1.f + __expf(-a.x)) * c.x;
    a.y = a.y / (1.f + __expf(-a.y)) * c.y;
    a.z = a.z / (1.f + __expf(-a.z)) * c.z;
    a.w = a.w / (1.f + __expf(-a.w)) * c.w;
    *(float4*)&g_t1[i] = a;
}

// ---------------- final combine ----------------
__global__ void combine_kernel(float* __restrict__ out) {
    int t = blockIdx.x;
    int d = threadIdx.x * 4;
    float w0 = g_tw[2 * t], w1 = g_tw[2 * t + 1];
    int s0 = g_slot[2 * t], s1 = g_slot[2 * t + 1];
    float4 hv = *(float4*)&g_h[(size_t)t * Dd + d];
    float4 a  = *(float4*)&g_g2[(size_t)s0 * Dd + d];
    float4 b  = *(float4*)&g_g2[(size_t)s1 * Dd + d];
    float4 ov;
    ov.x = hv.x + w0 * a.x + w1 * b.x;
    ov.y = hv.y + w0 * a.y + w1 * b.y;
    ov.z = hv.z + w0 * a.z + w1 * b.z;
    ov.w = hv.w + w0 * a.w + w1 * b.w;
    *(float4*)(out + (size_t)t * Dd + d) = ov;
}

// ---------------- launch ----------------
extern "C" void kernel_launch(void* const* d_in, const int* in_sizes, int n_in,
                              void* d_out, int out_size) {
    const float* x    = (const float*)d_in[0];
    const float* fcos = (const float*)d_in[3];
    const float* fsin = (const float*)d_in[4];
    const float* anw  = (const float*)d_in[5];
    const float* fnw  = (const float*)d_in[6];
    const float* wq   = (const float*)d_in[7];
    const float* wk   = (const float*)d_in[8];
    const float* wv   = (const float*)d_in[9];
    const float* wo   = (const float*)d_in[10];
    const float* gw   = (const float*)d_in[11];
    const float* w1e  = (const float*)d_in[12];
    const float* w2e  = (const float*)d_in[13];
    const float* w3e  = (const float*)d_in[14];
    float* out = (float*)d_out;

    void* p;
    float *xn, *qb, *kb, *vb, *ab, *hb, *hnb, *t1, *t3, *g2;
    cudaGetSymbolAddress(&p, g_xn); xn  = (float*)p;
    cudaGetSymbolAddress(&p, g_q);  qb  = (float*)p;
    cudaGetSymbolAddress(&p, g_k);  kb  = (float*)p;
    cudaGetSymbolAddress(&p, g_v);  vb  = (float*)p;
    cudaGetSymbolAddress(&p, g_at); ab  = (float*)p;
    cudaGetSymbolAddress(&p, g_h);  hb  = (float*)p;
    cudaGetSymbolAddress(&p, g_hn); hnb = (float*)p;
    cudaGetSymbolAddress(&p, g_t1); t1  = (float*)p;
    cudaGetSymbolAddress(&p, g_t3); t3  = (float*)p;
    cudaGetSymbolAddress(&p, g_g2); g2  = (float*)p;

    setup_kernel<<<1, 32>>>();

    rmsnorm_kernel<<<NTOK, 256>>>(x, anw, xn);

    dim3 gq(1024 / 128, NTOK / 128);
    tf32_gemm_kernel<<<gq, 256>>>(xn, wq, nullptr, qb, 1024, 1024);
    dim3 gk(256 / 128, NTOK / 128);
    tf32_gemm_kernel<<<gk, 256>>>(xn, wk, nullptr, kb, 256, 1024);
    tf32_gemm_kernel<<<gk, 256>>>(xn, wv, nullptr, vb, 256, 1024);

    rope_kernel<<<NTOK, Hh * 32>>>(qb, fcos, fsin, Hh);
    rope_kernel<<<NTOK, KHh * 32>>>(kb, fcos, fsin, KHh);

    dim3 ga(Ss / 32, Hh, Bb);
    attn_kernel<<<ga, 256>>>(qb, kb, vb, ab);

    tf32_gemm_kernel<<<gq, 256>>>(ab, wo, x, hb, 1024, 1024);

    rmsnorm_kernel<<<NTOK, 256>>>(hb, fnw, hnb);

    gate_kernel<<<NTOK / 4, 128>>>(hnb, gw);
    scan_kernel<<<1, 32>>>();
    initperm_kernel<<<(MAXROWS + 255) / 256, 256>>>();
    scatter_kernel<<<NTOK / 256, 256>>>();

    dim3 gm1(HIDd / 128, 32, Ee);
    tf32_moe_gemm_kernel<<<gm1, 256>>>(hnb, w1e, t1, HIDd, Dd, 1);
    tf32_moe_gemm_kernel<<<gm1, 256>>>(hnb, w3e, t3, HIDd, Dd, 1);

    silu_mul_kernel<<<((size_t)MAXROWS * HIDd) / 1024, 256>>>();

    dim3 gm2(Dd / 128, 32, Ee);
    tf32_moe_gemm_kernel<<<gm2, 256>>>(t1, w2e, g2, Dd, HIDd, 0);

    combine_kernel<<<NTOK, 256>>>(out);
}